// round 3
// baseline (speedup 1.0000x reference)
#include <cuda_runtime.h>
#include <math.h>

#define NMAX 50000
#define CAP  128

__device__ float g_bufA[NMAX * 32];
__device__ float g_bufB[NMAX * 32];
__device__ int2  g_csr[(size_t)NMAX * CAP];
__device__ int   g_cnt[NMAX];

__device__ __forceinline__ float selu_f(float x) {
    const float alpha = 1.6732632423543772f;
    const float scale = 1.0507009873554805f;
    return x > 0.f ? scale * x : scale * alpha * (expf(x) - 1.f);
}

typedef unsigned long long ull;
__device__ __forceinline__ void fma2(ull& d, ull a, ull b) {
    asm("fma.rn.f32x2 %0, %1, %2, %3;" : "=l"(d) : "l"(a), "l"(b), "l"(d));
}

// ---------------------------------------------------------------------------
// CSR build + pad-to-multiple-of-4 (zero-val entries multiply to nothing)
// ---------------------------------------------------------------------------
__global__ void __launch_bounds__(256) build_csr_kernel(const int* __restrict__ rows,
                                                        const int* __restrict__ cols,
                                                        const float* __restrict__ vals,
                                                        int E) {
    int e = blockIdx.x * 256 + threadIdx.x;
    if (e >= E) return;
    int r = rows[e];
    int pos = atomicAdd(&g_cnt[r], 1);
    if (pos < CAP)
        g_csr[(size_t)r * CAP + pos] = make_int2(cols[e], __float_as_int(vals[e]));
}

__global__ void __launch_bounds__(256) pad_csr_kernel(int N) {
    int r = blockIdx.x * 256 + threadIdx.x;
    if (r >= N) return;
    int c = g_cnt[r];
    if (c > CAP) c = CAP;
    int c4 = (c + 3) & ~3;
    for (int p = c; p < c4; p++)
        g_csr[(size_t)r * CAP + p] = make_int2(0, 0);
    g_cnt[r] = c4;
}

// ---------------------------------------------------------------------------
// GEMM1: sup = x[N,1024] @ w[1024,32]. FFMA2 packed over k-parity.
// acc f32x2: .x accumulates even-k products, .y odd-k; final add merges.
// ---------------------------------------------------------------------------
__global__ void __launch_bounds__(256) gemm1_kernel(const float* __restrict__ x,
                                                    const float* __restrict__ w,
                                                    float* __restrict__ sup, int N) {
    __shared__ float xs[128][34];    // stride 34 (even) -> 8B-aligned k-pairs
    __shared__ float ws_t[32][34];   // transposed: ws_t[col][k]

    int tid  = threadIdx.x;
    int row0 = blockIdx.x * 128;
    int trow = (tid >> 3) * 4;
    int tcol = (tid & 7) * 4;

    ull acc[4][4];
#pragma unroll
    for (int i = 0; i < 4; i++)
#pragma unroll
        for (int j = 0; j < 4; j++) acc[i][j] = 0ull;

    for (int k0 = 0; k0 < 1024; k0 += 32) {
        // w tile -> transposed smem
        {
            int kk   = tid >> 3;          // 0..31
            int col0 = (tid & 7) * 4;     // 0..28
            float4 v = *(const float4*)(w + (size_t)(k0 + kk) * 32 + col0);
            ws_t[col0][kk]     = v.x;
            ws_t[col0 + 1][kk] = v.y;
            ws_t[col0 + 2][kk] = v.z;
            ws_t[col0 + 3][kk] = v.w;
        }
        // x tile (row-major, k contiguous)
#pragma unroll
        for (int i = 0; i < 4; i++) {
            int idx = i * 256 + tid;
            int r   = idx >> 3;
            int kk  = (idx & 7) * 4;
            float4 v = make_float4(0.f, 0.f, 0.f, 0.f);
            if (row0 + r < N)
                v = *(const float4*)(x + (size_t)(row0 + r) * 1024 + k0 + kk);
            xs[r][kk] = v.x; xs[r][kk + 1] = v.y; xs[r][kk + 2] = v.z; xs[r][kk + 3] = v.w;
        }
        __syncthreads();

#pragma unroll
        for (int k = 0; k < 32; k += 2) {
            ull A[4], B[4];
#pragma unroll
            for (int i = 0; i < 4; i++) A[i] = *(const ull*)&xs[trow + i][k];
#pragma unroll
            for (int j = 0; j < 4; j++) B[j] = *(const ull*)&ws_t[tcol + j][k];
#pragma unroll
            for (int i = 0; i < 4; i++)
#pragma unroll
                for (int j = 0; j < 4; j++) fma2(acc[i][j], A[i], B[j]);
        }
        __syncthreads();
    }

#pragma unroll
    for (int i = 0; i < 4; i++) {
        int r = row0 + trow + i;
        if (r < N) {
            float o[4];
#pragma unroll
            for (int j = 0; j < 4; j++) {
                union { ull u; float2 f; } u; u.u = acc[i][j];
                o[j] = u.f.x + u.f.y;
            }
            *(float4*)(sup + (size_t)r * 32 + tcol) = make_float4(o[0], o[1], o[2], o[3]);
        }
    }
}

// ---------------------------------------------------------------------------
// SpMM core v3: 8 lanes per row, float4 per lane. No SHFL in hot loop.
// Meta loaded as int4 (2 edges); 4 independent LDG.128 gathers per step.
// ---------------------------------------------------------------------------
__device__ __forceinline__ float4 spmm_row4(const float* __restrict__ sup,
                                            int row, int sub) {
    int deg = g_cnt[row];                       // multiple of 4
    const int2* base = g_csr + (size_t)row * CAP;
    float4 acc = make_float4(0.f, 0.f, 0.f, 0.f);
    for (int e0 = 0; e0 < deg; e0 += 4) {
        int4 m01 = *(const int4*)(base + e0);
        int4 m23 = *(const int4*)(base + e0 + 2);
        const float4* s0 = (const float4*)(sup + (size_t)m01.x * 32) + sub;
        const float4* s1 = (const float4*)(sup + (size_t)m01.z * 32) + sub;
        const float4* s2 = (const float4*)(sup + (size_t)m23.x * 32) + sub;
        const float4* s3 = (const float4*)(sup + (size_t)m23.z * 32) + sub;
        float4 a = __ldg(s0), b = __ldg(s1), c = __ldg(s2), d = __ldg(s3);
        float v0 = __int_as_float(m01.y), v1 = __int_as_float(m01.w);
        float v2 = __int_as_float(m23.y), v3 = __int_as_float(m23.w);
        acc.x = fmaf(v0, a.x, acc.x); acc.y = fmaf(v0, a.y, acc.y);
        acc.z = fmaf(v0, a.z, acc.z); acc.w = fmaf(v0, a.w, acc.w);
        acc.x = fmaf(v1, b.x, acc.x); acc.y = fmaf(v1, b.y, acc.y);
        acc.z = fmaf(v1, b.z, acc.z); acc.w = fmaf(v1, b.w, acc.w);
        acc.x = fmaf(v2, c.x, acc.x); acc.y = fmaf(v2, c.y, acc.y);
        acc.z = fmaf(v2, c.z, acc.z); acc.w = fmaf(v2, c.w, acc.w);
        acc.x = fmaf(v3, d.x, acc.x); acc.y = fmaf(v3, d.y, acc.y);
        acc.z = fmaf(v3, d.z, acc.z); acc.w = fmaf(v3, d.w, acc.w);
    }
    return acc;
}

// ---------------------------------------------------------------------------
// Fused: agg = SpMM(sup_in); h = selu(agg)+b; sup_out = h @ w
// Block 256 = 8 warps = 32 rows (4 groups of 8 lanes per warp).
// ---------------------------------------------------------------------------
__global__ void __launch_bounds__(256) spmm_selu_gemm_kernel(const float* __restrict__ sup_in,
                                                             const float* __restrict__ bias,
                                                             const float* __restrict__ w,
                                                             float* __restrict__ sup_out,
                                                             int N) {
    __shared__ float ws[1024];
    __shared__ float bs[32];
    int tid = threadIdx.x;
    for (int i = tid; i < 1024; i += 256) ws[i] = w[i];
    if (tid < 32) bs[tid] = bias[tid];
    __syncthreads();

    int lane = tid & 31;
    int sub  = lane & 7;
    int row  = blockIdx.x * 32 + (tid >> 5) * 4 + (lane >> 3);
    if (row >= N) return;

    float4 a = spmm_row4(sup_in, row, sub);
    float4 h;
    h.x = selu_f(a.x) + bs[sub * 4];
    h.y = selu_f(a.y) + bs[sub * 4 + 1];
    h.z = selu_f(a.z) + bs[sub * 4 + 2];
    h.w = selu_f(a.w) + bs[sub * 4 + 3];

    float4 o = make_float4(0.f, 0.f, 0.f, 0.f);
    int gbase = lane & ~7;
#pragma unroll
    for (int k = 0; k < 32; k++) {
        float hc = (k & 3) == 0 ? h.x : (k & 3) == 1 ? h.y : (k & 3) == 2 ? h.z : h.w;
        float hk = __shfl_sync(0xffffffffu, hc, gbase | (k >> 2));
        float4 wv = *(const float4*)&ws[k * 32 + sub * 4];
        o.x = fmaf(hk, wv.x, o.x); o.y = fmaf(hk, wv.y, o.y);
        o.z = fmaf(hk, wv.z, o.z); o.w = fmaf(hk, wv.w, o.w);
    }
    *(float4*)(sup_out + (size_t)row * 32 + sub * 4) = o;
}

// ---------------------------------------------------------------------------
// Fused final: agg = SpMM; h = selu+b3; classifier heads.
// ---------------------------------------------------------------------------
__global__ void __launch_bounds__(256) spmm_final_kernel(const float* __restrict__ sup_in,
                                                         const float* __restrict__ bias,
                                                         const float* __restrict__ cw0,
                                                         const float* __restrict__ cb0,
                                                         const float* __restrict__ cw1,
                                                         const float* __restrict__ cb1,
                                                         float* __restrict__ out, int N) {
    int tid  = threadIdx.x;
    int lane = tid & 31;
    int sub  = lane & 7;
    int row  = blockIdx.x * 32 + (tid >> 5) * 4 + (lane >> 3);
    if (row >= N) return;

    float4 a = spmm_row4(sup_in, row, sub);
    const float4 b4 = *(const float4*)(bias + sub * 4);
    float4 h;
    h.x = selu_f(a.x) + b4.x;
    h.y = selu_f(a.y) + b4.y;
    h.z = selu_f(a.z) + b4.z;
    h.w = selu_f(a.w) + b4.w;

    float4 c0 = *(const float4*)(cw0 + sub * 4);
    float4 c1 = *(const float4*)(cw0 + 32 + sub * 4);
    float4 c2 = *(const float4*)(cw1 + sub * 4);
    float4 c3 = *(const float4*)(cw1 + 32 + sub * 4);
    float4 c4 = *(const float4*)(cw1 + 64 + sub * 4);

    float p0 = h.x * c0.x + h.y * c0.y + h.z * c0.z + h.w * c0.w;
    float p1 = h.x * c1.x + h.y * c1.y + h.z * c1.z + h.w * c1.w;
    float p2 = h.x * c2.x + h.y * c2.y + h.z * c2.z + h.w * c2.w;
    float p3 = h.x * c3.x + h.y * c3.y + h.z * c3.z + h.w * c3.w;
    float p4 = h.x * c4.x + h.y * c4.y + h.z * c4.z + h.w * c4.w;
#pragma unroll
    for (int off = 4; off; off >>= 1) {
        p0 += __shfl_xor_sync(0xffffffffu, p0, off);
        p1 += __shfl_xor_sync(0xffffffffu, p1, off);
        p2 += __shfl_xor_sync(0xffffffffu, p2, off);
        p3 += __shfl_xor_sync(0xffffffffu, p3, off);
        p4 += __shfl_xor_sync(0xffffffffu, p4, off);
    }
    if (sub == 0) {
        out[(size_t)row * 2]     = p0 + cb0[0];
        out[(size_t)row * 2 + 1] = p1 + cb0[1];
        size_t o1 = (size_t)N * 2 + (size_t)row * 3;
        out[o1]     = p2 + cb1[0];
        out[o1 + 1] = p3 + cb1[1];
        out[o1 + 2] = p4 + cb1[2];
    }
}

// ---------------------------------------------------------------------------
extern "C" void kernel_launch(void* const* d_in, const int* in_sizes, int n_in,
                              void* d_out, int out_size) {
    const float* x     = (const float*)d_in[0];
    const int*   arows = (const int*)d_in[1];
    const int*   acols = (const int*)d_in[2];
    const float* avals = (const float*)d_in[3];
    const float* w1    = (const float*)d_in[4];
    const float* b1    = (const float*)d_in[5];
    const float* w2    = (const float*)d_in[6];
    const float* b2    = (const float*)d_in[7];
    const float* w3    = (const float*)d_in[8];
    const float* b3    = (const float*)d_in[9];
    const float* cw0   = (const float*)d_in[10];
    const float* cb0   = (const float*)d_in[11];
    const float* cw1   = (const float*)d_in[12];
    const float* cb1   = (const float*)d_in[13];
    float* out = (float*)d_out;

    int N = in_sizes[0] / 1024;
    int E = in_sizes[1];

    float *bufA, *bufB;
    int* cnt;
    cudaGetSymbolAddress((void**)&bufA, g_bufA);
    cudaGetSymbolAddress((void**)&bufB, g_bufB);
    cudaGetSymbolAddress((void**)&cnt,  g_cnt);

    int gemmBlocks = (N + 127) / 128;
    int rowBlocks  = (N + 31) / 32;
    int edgeBlocks = (E + 255) / 256;
    int nBlocks    = (N + 255) / 256;

    cudaMemsetAsync(cnt, 0, (size_t)N * sizeof(int));
    build_csr_kernel<<<edgeBlocks, 256>>>(arows, acols, avals, E);
    pad_csr_kernel<<<nBlocks, 256>>>(N);

    gemm1_kernel<<<gemmBlocks, 256>>>(x, w1, bufA, N);
    spmm_selu_gemm_kernel<<<rowBlocks, 256>>>(bufA, b1, w2, bufB, N);
    spmm_selu_gemm_kernel<<<rowBlocks, 256>>>(bufB, b2, w3, bufA, N);
    spmm_final_kernel<<<rowBlocks, 256>>>(bufA, b3, cw0, cb0, cw1, cb1, out, N);
}

// round 5
// speedup vs baseline: 1.4526x; 1.4526x over previous
#include <cuda_runtime.h>
#include <math.h>

#define NMAX 50000
#define CAP  128

__device__ float g_bufA[NMAX * 32];
__device__ float g_bufB[NMAX * 32];
__device__ int2  g_csr[(size_t)NMAX * CAP];
__device__ int   g_cnt[NMAX];

__device__ __forceinline__ float selu_f(float x) {
    const float alpha = 1.6732632423543772f;
    const float scale = 1.0507009873554805f;
    return x > 0.f ? scale * x : scale * alpha * (expf(x) - 1.f);
}

typedef unsigned long long ull;
__device__ __forceinline__ ull pack2(float a) {
    ull r; asm("mov.b64 %0, {%1, %1};" : "=l"(r) : "f"(a)); return r;
}
__device__ __forceinline__ void fma2(ull& d, ull a, ull b) {
    asm("fma.rn.f32x2 %0, %1, %2, %3;" : "=l"(d) : "l"(a), "l"(b), "l"(d));
}

// ---------------------------------------------------------------------------
// CSR build
// ---------------------------------------------------------------------------
__global__ void __launch_bounds__(256) build_csr_kernel(const int* __restrict__ rows,
                                                        const int* __restrict__ cols,
                                                        const float* __restrict__ vals,
                                                        int E) {
    int e = blockIdx.x * 256 + threadIdx.x;
    if (e >= E) return;
    int r = rows[e];
    int pos = atomicAdd(&g_cnt[r], 1);
    if (pos < CAP)
        g_csr[(size_t)r * CAP + pos] = make_int2(cols[e], __float_as_int(vals[e]));
}

// ---------------------------------------------------------------------------
// GEMM1 (Round-2 measured-good version): sup = x @ w, FFMA2 col-pair packing.
// ---------------------------------------------------------------------------
__global__ void __launch_bounds__(256) gemm1_kernel(const float* __restrict__ x,
                                                    const float* __restrict__ w,
                                                    float* __restrict__ sup, int N) {
    __shared__ float xs[128][33];
    __shared__ float ws[32][32];

    int tid  = threadIdx.x;
    int row0 = blockIdx.x * 128;
    int trow = (tid >> 3) * 4;
    int tcol = (tid & 7) * 4;

    ull acc[4][2];
#pragma unroll
    for (int i = 0; i < 4; i++) { acc[i][0] = 0ull; acc[i][1] = 0ull; }

    for (int k0 = 0; k0 < 1024; k0 += 32) {
        {
            float4 v = ((const float4*)(w + (size_t)k0 * 32))[tid];
            ((float4*)ws)[tid] = v;
        }
#pragma unroll
        for (int i = 0; i < 4; i++) {
            int idx = i * 256 + tid;
            int r   = idx >> 3;
            int kk  = (idx & 7) * 4;
            float4 v = make_float4(0.f, 0.f, 0.f, 0.f);
            if (row0 + r < N)
                v = *(const float4*)(x + (size_t)(row0 + r) * 1024 + k0 + kk);
            xs[r][kk] = v.x; xs[r][kk + 1] = v.y; xs[r][kk + 2] = v.z; xs[r][kk + 3] = v.w;
        }
        __syncthreads();

#pragma unroll
        for (int k = 0; k < 32; k++) {
            ull B0 = *(const ull*)&ws[k][tcol];
            ull B1 = *(const ull*)&ws[k][tcol + 2];
#pragma unroll
            for (int i = 0; i < 4; i++) {
                ull A = pack2(xs[trow + i][k]);
                fma2(acc[i][0], A, B0);
                fma2(acc[i][1], A, B1);
            }
        }
        __syncthreads();
    }

#pragma unroll
    for (int i = 0; i < 4; i++) {
        int r = row0 + trow + i;
        if (r < N) {
            union { ull u; float2 f; } u0, u1;
            u0.u = acc[i][0]; u1.u = acc[i][1];
            *(float4*)(sup + (size_t)r * 32 + tcol) =
                make_float4(u0.f.x, u0.f.y, u1.f.x, u1.f.y);
        }
    }
}

// ---------------------------------------------------------------------------
// SpMM core: warp per row, smem-staged meta (no SHFL in hot loop).
// stage: per-warp 32-entry int2 buffer in shared memory.
// ---------------------------------------------------------------------------
__device__ __forceinline__ float spmm_row_staged(const float* __restrict__ sup,
                                                 int row, int lane,
                                                 int2* __restrict__ stage) {
    int deg = g_cnt[row];
    if (deg > CAP) deg = CAP;
    const int2* base = g_csr + (size_t)row * CAP;
    float acc = 0.f;

    for (int c0 = 0; c0 < deg; c0 += 32) {
        int rem = deg - c0;
        if (rem > 32) rem = 32;
        if (lane < rem) stage[lane] = base[c0 + lane];
        __syncwarp();

        int j = 0;
        for (; j + 8 <= rem; j += 8) {
            int2 e0 = stage[j],     e1 = stage[j + 1];
            int2 e2 = stage[j + 2], e3 = stage[j + 3];
            int2 e4 = stage[j + 4], e5 = stage[j + 5];
            int2 e6 = stage[j + 6], e7 = stage[j + 7];
            float s0 = __ldg(sup + ((size_t)e0.x << 5) + lane);
            float s1 = __ldg(sup + ((size_t)e1.x << 5) + lane);
            float s2 = __ldg(sup + ((size_t)e2.x << 5) + lane);
            float s3 = __ldg(sup + ((size_t)e3.x << 5) + lane);
            float s4 = __ldg(sup + ((size_t)e4.x << 5) + lane);
            float s5 = __ldg(sup + ((size_t)e5.x << 5) + lane);
            float s6 = __ldg(sup + ((size_t)e6.x << 5) + lane);
            float s7 = __ldg(sup + ((size_t)e7.x << 5) + lane);
            acc = fmaf(__int_as_float(e0.y), s0, acc);
            acc = fmaf(__int_as_float(e1.y), s1, acc);
            acc = fmaf(__int_as_float(e2.y), s2, acc);
            acc = fmaf(__int_as_float(e3.y), s3, acc);
            acc = fmaf(__int_as_float(e4.y), s4, acc);
            acc = fmaf(__int_as_float(e5.y), s5, acc);
            acc = fmaf(__int_as_float(e6.y), s6, acc);
            acc = fmaf(__int_as_float(e7.y), s7, acc);
        }
        for (; j < rem; j++) {
            int2 e = stage[j];
            acc = fmaf(__int_as_float(e.y), __ldg(sup + ((size_t)e.x << 5) + lane), acc);
        }
        __syncwarp();
    }
    return acc;
}

// ---------------------------------------------------------------------------
// Fused: agg = SpMM(sup_in); h = selu(agg)+b; sup_out = h @ w   (warp per row)
// ---------------------------------------------------------------------------
__global__ void __launch_bounds__(256) spmm_selu_gemm_kernel(const float* __restrict__ sup_in,
                                                             const float* __restrict__ bias,
                                                             const float* __restrict__ w,
                                                             float* __restrict__ sup_out,
                                                             int N) {
    __shared__ float ws[1024];
    __shared__ float bs[32];
    __shared__ int2  stage[8][32];
    int tid = threadIdx.x;
    for (int i = tid; i < 1024; i += 256) ws[i] = w[i];
    if (tid < 32) bs[tid] = bias[tid];
    __syncthreads();

    int warp = tid >> 5;
    int lane = tid & 31;
    int row  = blockIdx.x * 8 + warp;
    if (row >= N) return;

    float acc = spmm_row_staged(sup_in, row, lane, stage[warp]);
    float h = selu_f(acc) + bs[lane];

    float o = 0.f;
#pragma unroll
    for (int k = 0; k < 32; k++) {
        float hk = __shfl_sync(0xffffffffu, h, k);
        o = fmaf(hk, ws[k * 32 + lane], o);
    }
    sup_out[(size_t)row * 32 + lane] = o;
}

// ---------------------------------------------------------------------------
// Fused final: agg = SpMM; h = selu+b3; classifier heads → out
// ---------------------------------------------------------------------------
__global__ void __launch_bounds__(256) spmm_final_kernel(const float* __restrict__ sup_in,
                                                         const float* __restrict__ bias,
                                                         const float* __restrict__ cw0,
                                                         const float* __restrict__ cb0,
                                                         const float* __restrict__ cw1,
                                                         const float* __restrict__ cb1,
                                                         float* __restrict__ out, int N) {
    __shared__ int2 stage[8][32];
    int tid  = threadIdx.x;
    int warp = tid >> 5;
    int lane = tid & 31;
    int row  = blockIdx.x * 8 + warp;
    if (row >= N) return;

    float acc = spmm_row_staged(sup_in, row, lane, stage[warp]);
    float h = selu_f(acc) + bias[lane];

    float p0 = h * cw0[lane];
    float p1 = h * cw0[32 + lane];
    float p2 = h * cw1[lane];
    float p3 = h * cw1[32 + lane];
    float p4 = h * cw1[64 + lane];
#pragma unroll
    for (int off = 16; off; off >>= 1) {
        p0 += __shfl_xor_sync(0xffffffffu, p0, off);
        p1 += __shfl_xor_sync(0xffffffffu, p1, off);
        p2 += __shfl_xor_sync(0xffffffffu, p2, off);
        p3 += __shfl_xor_sync(0xffffffffu, p3, off);
        p4 += __shfl_xor_sync(0xffffffffu, p4, off);
    }
    if (lane < 2) {
        out[(size_t)row * 2 + lane] = ((lane == 0) ? p0 : p1) + cb0[lane];
    } else if (lane < 5) {
        float pv = (lane == 2) ? p2 : ((lane == 3) ? p3 : p4);
        out[(size_t)N * 2 + (size_t)row * 3 + (lane - 2)] = pv + cb1[lane - 2];
    }
}

// ---------------------------------------------------------------------------
extern "C" void kernel_launch(void* const* d_in, const int* in_sizes, int n_in,
                              void* d_out, int out_size) {
    const float* x     = (const float*)d_in[0];
    const int*   arows = (const int*)d_in[1];
    const int*   acols = (const int*)d_in[2];
    const float* avals = (const float*)d_in[3];
    const float* w1    = (const float*)d_in[4];
    const float* b1    = (const float*)d_in[5];
    const float* w2    = (const float*)d_in[6];
    const float* b2    = (const float*)d_in[7];
    const float* w3    = (const float*)d_in[8];
    const float* b3    = (const float*)d_in[9];
    const float* cw0   = (const float*)d_in[10];
    const float* cb0   = (const float*)d_in[11];
    const float* cw1   = (const float*)d_in[12];
    const float* cb1   = (const float*)d_in[13];
    float* out = (float*)d_out;

    int N = in_sizes[0] / 1024;
    int E = in_sizes[1];

    float *bufA, *bufB;
    int* cnt;
    cudaGetSymbolAddress((void**)&bufA, g_bufA);
    cudaGetSymbolAddress((void**)&bufB, g_bufB);
    cudaGetSymbolAddress((void**)&cnt,  g_cnt);

    int gemmBlocks = (N + 127) / 128;
    int rowBlocks  = (N + 7) / 8;
    int edgeBlocks = (E + 255) / 256;

    cudaMemsetAsync(cnt, 0, (size_t)N * sizeof(int));
    build_csr_kernel<<<edgeBlocks, 256>>>(arows, acols, avals, E);

    gemm1_kernel<<<gemmBlocks, 256>>>(x, w1, bufA, N);
    spmm_selu_gemm_kernel<<<rowBlocks, 256>>>(bufA, b1, w2, bufB, N);
    spmm_selu_gemm_kernel<<<rowBlocks, 256>>>(bufB, b2, w3, bufA, N);
    spmm_final_kernel<<<rowBlocks, 256>>>(bufA, b3, cw0, cb0, cw1, cb1, out, N);
}

// round 7
// speedup vs baseline: 2.0675x; 1.4233x over previous
#include <cuda_runtime.h>
#include <math.h>

#define NMAX 50000
#define CAP  128

__device__ float g_bufA[NMAX * 32];
__device__ float g_bufB[NMAX * 32];
__device__ int2  g_csr[(size_t)NMAX * CAP];
__device__ int   g_cnt[NMAX];

__device__ __forceinline__ float selu_f(float x) {
    const float alpha = 1.6732632423543772f;
    const float scale = 1.0507009873554805f;
    return x > 0.f ? scale * x : scale * alpha * (expf(x) - 1.f);
}

typedef unsigned long long ull;
__device__ __forceinline__ ull pack2(float a) {
    ull r; asm("mov.b64 %0, {%1, %1};" : "=l"(r) : "f"(a)); return r;
}
__device__ __forceinline__ void fma2(ull& d, ull a, ull b) {
    asm("fma.rn.f32x2 %0, %1, %2, %3;" : "=l"(d) : "l"(a), "l"(b), "l"(d));
}

// ---------------------------------------------------------------------------
// CSR build
// ---------------------------------------------------------------------------
__global__ void __launch_bounds__(256) build_csr_kernel(const int* __restrict__ rows,
                                                        const int* __restrict__ cols,
                                                        const float* __restrict__ vals,
                                                        int E) {
    int e = blockIdx.x * 256 + threadIdx.x;
    if (e >= E) return;
    int r = rows[e];
    int pos = atomicAdd(&g_cnt[r], 1);
    if (pos < CAP)
        g_csr[(size_t)r * CAP + pos] = make_int2(cols[e], __float_as_int(vals[e]));
}

// ---------------------------------------------------------------------------
// GEMM1: sup = x[N,1024] @ w[1024,32]. Same col-pair FFMA2 packing as the
// measured-good R2 kernel; thread tile widened to 4 rows x 8 cols (128 thr).
// Per k per thread: 4 LDS.64(B) + 4 LDS.32(A) + 4 mov + 16 FFMA2.
// ---------------------------------------------------------------------------
__global__ void __launch_bounds__(128) gemm1_kernel(const float* __restrict__ x,
                                                    const float* __restrict__ w,
                                                    float* __restrict__ sup, int N) {
    __shared__ float xs[128][33];
    __shared__ float ws[32][32];

    int tid  = threadIdx.x;
    int row0 = blockIdx.x * 128;
    int trow = (tid >> 2) * 4;      // 0..124
    int tcol = (tid & 3) * 8;       // 0,8,16,24

    ull acc[4][4];
#pragma unroll
    for (int i = 0; i < 4; i++)
#pragma unroll
        for (int j = 0; j < 4; j++) acc[i][j] = 0ull;

    for (int k0 = 0; k0 < 1024; k0 += 32) {
        // w tile: 256 float4 over 128 threads
#pragma unroll
        for (int i = 0; i < 2; i++) {
            int idx = i * 128 + tid;
            ((float4*)ws)[idx] = ((const float4*)(w + (size_t)k0 * 32))[idx];
        }
        // x tile: 1024 float4 over 128 threads
#pragma unroll
        for (int i = 0; i < 8; i++) {
            int idx = i * 128 + tid;
            int r   = idx >> 3;
            int kk  = (idx & 7) * 4;
            float4 v = make_float4(0.f, 0.f, 0.f, 0.f);
            if (row0 + r < N)
                v = *(const float4*)(x + (size_t)(row0 + r) * 1024 + k0 + kk);
            xs[r][kk] = v.x; xs[r][kk + 1] = v.y; xs[r][kk + 2] = v.z; xs[r][kk + 3] = v.w;
        }
        __syncthreads();

#pragma unroll
        for (int k = 0; k < 32; k++) {
            ull B[4];
#pragma unroll
            for (int j = 0; j < 4; j++) B[j] = *(const ull*)&ws[k][tcol + 2 * j];
#pragma unroll
            for (int i = 0; i < 4; i++) {
                ull A = pack2(xs[trow + i][k]);
                fma2(acc[i][0], A, B[0]);
                fma2(acc[i][1], A, B[1]);
                fma2(acc[i][2], A, B[2]);
                fma2(acc[i][3], A, B[3]);
            }
        }
        __syncthreads();
    }

#pragma unroll
    for (int i = 0; i < 4; i++) {
        int r = row0 + trow + i;
        if (r < N) {
            union { ull u; float2 f; } u0, u1, u2, u3;
            u0.u = acc[i][0]; u1.u = acc[i][1]; u2.u = acc[i][2]; u3.u = acc[i][3];
            *(float4*)(sup + (size_t)r * 32 + tcol) =
                make_float4(u0.f.x, u0.f.y, u1.f.x, u1.f.y);
            *(float4*)(sup + (size_t)r * 32 + tcol + 4) =
                make_float4(u2.f.x, u2.f.y, u3.f.x, u3.f.y);
        }
    }
}

// ---------------------------------------------------------------------------
// SpMM core (R2 measured-good): warp per row, SHFL broadcast, unroll 8.
// ---------------------------------------------------------------------------
__device__ __forceinline__ float spmm_row(const float* __restrict__ sup,
                                          int row, int lane) {
    int deg = g_cnt[row];
    if (deg > CAP) deg = CAP;
    const int2* base = g_csr + (size_t)row * CAP;
    float acc = 0.f;
    for (int c0 = 0; c0 < deg; c0 += 32) {
        int rem = deg - c0;
        int2 ev = make_int2(0, 0);
        if (lane < rem) ev = base[c0 + lane];
        if (rem >= 32) {
#pragma unroll
            for (int b = 0; b < 4; b++) {
                float s[8], vv[8];
#pragma unroll
                for (int j = 0; j < 8; j++) {
                    int   col = __shfl_sync(0xffffffffu, ev.x, b * 8 + j);
                    vv[j] = __int_as_float(__shfl_sync(0xffffffffu, ev.y, b * 8 + j));
                    s[j] = __ldg(sup + (size_t)col * 32 + lane);
                }
#pragma unroll
                for (int j = 0; j < 8; j++) acc = fmaf(vv[j], s[j], acc);
            }
        } else {
            for (int j = 0; j < rem; j++) {
                int   col = __shfl_sync(0xffffffffu, ev.x, j);
                float v   = __int_as_float(__shfl_sync(0xffffffffu, ev.y, j));
                acc = fmaf(v, __ldg(sup + (size_t)col * 32 + lane), acc);
            }
        }
    }
    return acc;
}

// ---------------------------------------------------------------------------
// Fused: agg = SpMM(sup_in); h = selu(agg)+b; sup_out = h @ w
// ---------------------------------------------------------------------------
__global__ void __launch_bounds__(256) spmm_selu_gemm_kernel(const float* __restrict__ sup_in,
                                                             const float* __restrict__ bias,
                                                             const float* __restrict__ w,
                                                             float* __restrict__ sup_out,
                                                             int N) {
    __shared__ float ws[1024];
    __shared__ float bs[32];
    int tid = threadIdx.x;
    for (int i = tid; i < 1024; i += 256) ws[i] = w[i];
    if (tid < 32) bs[tid] = bias[tid];
    __syncthreads();

    int warp = tid >> 5;
    int lane = tid & 31;
    int row  = blockIdx.x * 8 + warp;
    if (row >= N) return;

    float acc = spmm_row(sup_in, row, lane);
    float h = selu_f(acc) + bs[lane];

    float o = 0.f;
#pragma unroll
    for (int k = 0; k < 32; k++) {
        float hk = __shfl_sync(0xffffffffu, h, k);
        o = fmaf(hk, ws[k * 32 + lane], o);
    }
    sup_out[(size_t)row * 32 + lane] = o;
}

// ---------------------------------------------------------------------------
// Fused final: agg = SpMM; h = selu+b3; classifier heads → out
// ---------------------------------------------------------------------------
__global__ void __launch_bounds__(256) spmm_final_kernel(const float* __restrict__ sup_in,
                                                         const float* __restrict__ bias,
                                                         const float* __restrict__ cw0,
                                                         const float* __restrict__ cb0,
                                                         const float* __restrict__ cw1,
                                                         const float* __restrict__ cb1,
                                                         float* __restrict__ out, int N) {
    int tid  = threadIdx.x;
    int warp = tid >> 5;
    int lane = tid & 31;
    int row  = blockIdx.x * 8 + warp;
    if (row >= N) return;

    float acc = spmm_row(sup_in, row, lane);
    float h = selu_f(acc) + bias[lane];

    float p0 = h * cw0[lane];
    float p1 = h * cw0[32 + lane];
    float p2 = h * cw1[lane];
    float p3 = h * cw1[32 + lane];
    float p4 = h * cw1[64 + lane];
#pragma unroll
    for (int off = 16; off; off >>= 1) {
        p0 += __shfl_xor_sync(0xffffffffu, p0, off);
        p1 += __shfl_xor_sync(0xffffffffu, p1, off);
        p2 += __shfl_xor_sync(0xffffffffu, p2, off);
        p3 += __shfl_xor_sync(0xffffffffu, p3, off);
        p4 += __shfl_xor_sync(0xffffffffu, p4, off);
    }
    if (lane < 2) {
        out[(size_t)row * 2 + lane] = ((lane == 0) ? p0 : p1) + cb0[lane];
    } else if (lane < 5) {
        float pv = (lane == 2) ? p2 : ((lane == 3) ? p3 : p4);
        out[(size_t)N * 2 + (size_t)row * 3 + (lane - 2)] = pv + cb1[lane - 2];
    }
}

// ---------------------------------------------------------------------------
extern "C" void kernel_launch(void* const* d_in, const int* in_sizes, int n_in,
                              void* d_out, int out_size) {
    const float* x     = (const float*)d_in[0];
    const int*   arows = (const int*)d_in[1];
    const int*   acols = (const int*)d_in[2];
    const float* avals = (const float*)d_in[3];
    const float* w1    = (const float*)d_in[4];
    const float* b1    = (const float*)d_in[5];
    const float* w2    = (const float*)d_in[6];
    const float* b2    = (const float*)d_in[7];
    const float* w3    = (const float*)d_in[8];
    const float* b3    = (const float*)d_in[9];
    const float* cw0   = (const float*)d_in[10];
    const float* cb0   = (const float*)d_in[11];
    const float* cw1   = (const float*)d_in[12];
    const float* cb1   = (const float*)d_in[13];
    float* out = (float*)d_out;

    int N = in_sizes[0] / 1024;
    int E = in_sizes[1];

    float *bufA, *bufB;
    int* cnt;
    cudaGetSymbolAddress((void**)&bufA, g_bufA);
    cudaGetSymbolAddress((void**)&bufB, g_bufB);
    cudaGetSymbolAddress((void**)&cnt,  g_cnt);

    int gemmBlocks = (N + 127) / 128;
    int rowBlocks  = (N + 7) / 8;
    int edgeBlocks = (E + 255) / 256;

    cudaMemsetAsync(cnt, 0, (size_t)N * sizeof(int));
    build_csr_kernel<<<edgeBlocks, 256>>>(arows, acols, avals, E);

    gemm1_kernel<<<gemmBlocks, 128>>>(x, w1, bufA, N);
    spmm_selu_gemm_kernel<<<rowBlocks, 256>>>(bufA, b1, w2, bufB, N);
    spmm_selu_gemm_kernel<<<rowBlocks, 256>>>(bufB, b2, w3, bufA, N);
    spmm_final_kernel<<<rowBlocks, 256>>>(bufA, b3, cw0, cb0, cw1, cb1, out, N);
}